// round 11
// baseline (speedup 1.0000x reference)
#include <cuda_runtime.h>

#define NN   50000
#define TOPK 32
#define INC  128
#define OUTC 64
#define NEG_SLOPE 0.2f
#define BN_EPS 1e-5f

// ---------------- scratch (no allocations allowed) ----------------
__device__ float g_xlin[NN * OUTC];
__device__ float g_si[NN];
__device__ float g_sj[NN];
__device__ float g_pre[NN * OUTC];
__device__ float g_sum[OUTC];
__device__ float g_sumsq[OUTC];
__device__ int   g_is64;

// ---------------- f32x2 helpers (sm_100+ packed fp32) ----------------
__device__ __forceinline__ unsigned long long pack2(float a) {
    unsigned long long r;
    asm("mov.b64 %0, {%1, %1};" : "=l"(r) : "f"(a));
    return r;
}
__device__ __forceinline__ void ffma2(unsigned long long& c,
                                      unsigned long long a, unsigned long long b) {
    asm("fma.rn.f32x2 %0, %1, %2, %0;" : "+l"(c) : "l"(a), "l"(b));
}
__device__ __forceinline__ float2 u2f(unsigned long long v) {
    float2 f;
    asm("mov.b64 {%0, %1}, %2;" : "=f"(f.x), "=f"(f.y) : "l"(v));
    return f;
}

// ---------------- GEMM: x_lin = x @ W^T (R9-proven) ----------------
__global__ void __launch_bounds__(256) k_gemm(const float* __restrict__ x,
                                              const float* __restrict__ w,
                                              const int* __restrict__ ei32) {
    __shared__ float Ws[INC][68];
    __shared__ float xs[16][132];

    const int tid = threadIdx.x;
    const int m0  = blockIdx.x * 128;

    if (blockIdx.x == 0) {
        if (tid < OUTC) { g_sum[tid] = 0.f; g_sumsq[tid] = 0.f; }
        if (tid == 0) {
            int any = 0;
            #pragma unroll 1
            for (int i = 1; i < 128; i += 2) any |= ei32[i];
            g_is64 = (any == 0) ? 1 : 0;
        }
    }

    for (int idx = tid; idx < OUTC * INC; idx += 256) {
        int n = idx >> 7, k = idx & 127;
        Ws[k][n] = w[idx];
    }

    const int rg = tid & 31;
    const int cg = tid >> 5;

    unsigned long long acc[4][4];
    #pragma unroll
    for (int i = 0; i < 4; i++)
        #pragma unroll
        for (int j = 0; j < 4; j++) acc[i][j] = 0ull;

    for (int kc = 0; kc < INC; kc += 16) {
        __syncthreads();
        #pragma unroll
        for (int rr = 0; rr < 2; rr++) {
            int row = ((tid >> 2) & 63) + rr * 64;
            int k4  = (tid & 3) * 4;
            int gr  = m0 + row;
            float4 v = make_float4(0.f, 0.f, 0.f, 0.f);
            if (gr < NN) v = *(const float4*)&x[gr * INC + kc + k4];
            xs[k4 + 0][row] = v.x;
            xs[k4 + 1][row] = v.y;
            xs[k4 + 2][row] = v.z;
            xs[k4 + 3][row] = v.w;
        }
        __syncthreads();

        #pragma unroll
        for (int k = 0; k < 16; k++) {
            float4 a = *(const float4*)&xs[k][rg * 4];
            const ulonglong2* bp = (const ulonglong2*)&Ws[kc + k][cg * 8];
            ulonglong2 bA = bp[0];
            ulonglong2 bB = bp[1];
            unsigned long long bv[4] = {bA.x, bA.y, bB.x, bB.y};
            unsigned long long av[4] = {pack2(a.x), pack2(a.y), pack2(a.z), pack2(a.w)};
            #pragma unroll
            for (int i = 0; i < 4; i++)
                #pragma unroll
                for (int j = 0; j < 4; j++)
                    ffma2(acc[i][j], av[i], bv[j]);
        }
    }

    #pragma unroll
    for (int i = 0; i < 4; i++) {
        int m = m0 + rg * 4 + i;
        if (m < NN) {
            float2 p0 = u2f(acc[i][0]), p1 = u2f(acc[i][1]);
            float2 p2 = u2f(acc[i][2]), p3 = u2f(acc[i][3]);
            *(float4*)&g_xlin[m * OUTC + cg * 8]     = make_float4(p0.x, p0.y, p1.x, p1.y);
            *(float4*)&g_xlin[m * OUTC + cg * 8 + 4] = make_float4(p2.x, p2.y, p3.x, p3.y);
        }
    }
}

// ---------------- per-node attention scalars ----------------
__global__ void __launch_bounds__(256) k_scal(const float* __restrict__ emb,
                                              const float* __restrict__ ai,
                                              const float* __restrict__ aj,
                                              const float* __restrict__ aei,
                                              const float* __restrict__ aej) {
    int wrow = blockIdx.x * 8 + (threadIdx.x >> 5);
    int lane = threadIdx.x & 31;
    if (wrow >= NN) return;
    float x0 = g_xlin[wrow * OUTC + lane];
    float x1 = g_xlin[wrow * OUTC + 32 + lane];
    float e0 = emb[wrow * OUTC + lane];
    float e1 = emb[wrow * OUTC + 32 + lane];
    float si = x0 * ai[lane] + x1 * ai[lane + 32] + e0 * aei[lane] + e1 * aei[lane + 32];
    float sj = x0 * aj[lane] + x1 * aj[lane + 32] + e0 * aej[lane] + e1 * aej[lane + 32];
    #pragma unroll
    for (int o = 16; o; o >>= 1) {
        si += __shfl_xor_sync(0xffffffffu, si, o);
        sj += __shfl_xor_sync(0xffffffffu, sj, o);
    }
    if (lane == 0) { g_si[wrow] = si; g_sj[wrow] = sj; }
}

// ---------------- softmax + gather: one WARP per node, fp32 float2, MLP=8 ----
__global__ void __launch_bounds__(64) k_agg(const void* __restrict__ ei,
                                            const float* __restrict__ bias) {
    const int wid  = threadIdx.x >> 5;
    const int lane = threadIdx.x & 31;
    const int n    = blockIdx.x * 2 + wid;

    __shared__ float2 spack[2][34];

    int src;
    if (g_is64) src = (int)((const long long*)ei)[(long long)n * TOPK + lane];
    else        src = ((const int*)ei)[n * TOPK + lane];
    float si  = g_si[n];
    float sjn = g_sj[n];
    float a = si + g_sj[src];
    a = (a >= 0.f) ? a : NEG_SLOPE * a;
    float aself = si + sjn;
    aself = (aself >= 0.f) ? aself : NEG_SLOPE * aself;

    float m = fmaxf(a, aself);
    #pragma unroll
    for (int o = 16; o; o >>= 1) m = fmaxf(m, __shfl_xor_sync(0xffffffffu, m, o));
    float ex  = __expf(a - m);
    float exs = __expf(aself - m);
    float ssum = ex;
    #pragma unroll
    for (int o = 16; o; o >>= 1) ssum += __shfl_xor_sync(0xffffffffu, ssum, o);
    ssum += exs;
    float inv = 1.f / (ssum + 1e-16f);
    spack[wid][lane] = make_float2(ex * inv, __int_as_float(src));
    if (lane == 0) spack[wid][32] = make_float2(exs * inv, __int_as_float(n));
    __syncwarp();

    unsigned long long acc = 0ull;
    #pragma unroll
    for (int c0 = 0; c0 < TOPK; c0 += 8) {
        float2 p[8];
        #pragma unroll
        for (int c = 0; c < 8; c++) p[c] = spack[wid][c0 + c];
        unsigned long long v[8];
        #pragma unroll
        for (int c = 0; c < 8; c++) {
            int s = __float_as_int(p[c].y);
            v[c] = *(const unsigned long long*)&g_xlin[s * OUTC + lane * 2];
        }
        #pragma unroll
        for (int c = 0; c < 8; c++) ffma2(acc, pack2(p[c].x), v[c]);
    }
    {
        float2 p = spack[wid][32];
        int s = __float_as_int(p.y);
        unsigned long long v = *(const unsigned long long*)&g_xlin[s * OUTC + lane * 2];
        ffma2(acc, pack2(p.x), v);
    }
    float2 r  = u2f(acc);
    float2 b2 = *(const float2*)&bias[lane * 2];
    r.x += b2.x;
    r.y += b2.y;
    *(float2*)&g_pre[n * OUTC + lane * 2] = r;
}

// ---------------- BN reduction: 148 blocks x 1024 threads (occupancy fix) ----------------
__global__ void __launch_bounds__(1024) k_red() {
    __shared__ float4 sa[1024], sb[1024];
    const int tid = threadIdx.x;
    const int T = gridDim.x * 1024;              // 148*1024 = 151552, mult of 16
    const int NE = NN * OUTC / 4;                // 800000 float4
    float4 s  = make_float4(0.f, 0.f, 0.f, 0.f);
    float4 s2 = make_float4(0.f, 0.f, 0.f, 0.f);

    int i = blockIdx.x * 1024 + tid;
    for (; i + 3 * T < NE; i += 4 * T) {
        float4 v0 = *(const float4*)&g_pre[(i        ) * 4];
        float4 v1 = *(const float4*)&g_pre[(i + T    ) * 4];
        float4 v2 = *(const float4*)&g_pre[(i + 2 * T) * 4];
        float4 v3 = *(const float4*)&g_pre[(i + 3 * T) * 4];
        s.x += v0.x + v1.x + v2.x + v3.x;
        s.y += v0.y + v1.y + v2.y + v3.y;
        s.z += v0.z + v1.z + v2.z + v3.z;
        s.w += v0.w + v1.w + v2.w + v3.w;
        s2.x = fmaf(v0.x, v0.x, fmaf(v1.x, v1.x, fmaf(v2.x, v2.x, fmaf(v3.x, v3.x, s2.x))));
        s2.y = fmaf(v0.y, v0.y, fmaf(v1.y, v1.y, fmaf(v2.y, v2.y, fmaf(v3.y, v3.y, s2.y))));
        s2.z = fmaf(v0.z, v0.z, fmaf(v1.z, v1.z, fmaf(v2.z, v2.z, fmaf(v3.z, v3.z, s2.z))));
        s2.w = fmaf(v0.w, v0.w, fmaf(v1.w, v1.w, fmaf(v2.w, v2.w, fmaf(v3.w, v3.w, s2.w))));
    }
    for (; i < NE; i += T) {
        float4 v = *(const float4*)&g_pre[i * 4];
        s.x += v.x; s.y += v.y; s.z += v.z; s.w += v.w;
        s2.x = fmaf(v.x, v.x, s2.x);
        s2.y = fmaf(v.y, v.y, s2.y);
        s2.z = fmaf(v.z, v.z, s2.z);
        s2.w = fmaf(v.w, v.w, s2.w);
    }
    sa[tid] = s; sb[tid] = s2;
    __syncthreads();
    #pragma unroll
    for (int off = 512; off >= 16; off >>= 1) {
        if (tid < off) {
            float4 qa = sa[tid + off], qb = sb[tid + off];
            float4 ra = sa[tid],       rb = sb[tid];
            ra.x += qa.x; ra.y += qa.y; ra.z += qa.z; ra.w += qa.w;
            rb.x += qb.x; rb.y += qb.y; rb.z += qb.z; rb.w += qb.w;
            sa[tid] = ra; sb[tid] = rb;
        }
        __syncthreads();
    }
    if (tid < 16) {
        float4 ra = sa[tid], rb = sb[tid];
        int c = tid * 4;
        atomicAdd(&g_sum[c],     ra.x);
        atomicAdd(&g_sum[c + 1], ra.y);
        atomicAdd(&g_sum[c + 2], ra.z);
        atomicAdd(&g_sum[c + 3], ra.w);
        atomicAdd(&g_sumsq[c],     rb.x);
        atomicAdd(&g_sumsq[c + 1], rb.y);
        atomicAdd(&g_sumsq[c + 2], rb.z);
        atomicAdd(&g_sumsq[c + 3], rb.w);
    }
}

// ---------------- BN stats (inline) + apply + ReLU ----------------
__global__ void __launch_bounds__(256) k_bn(const float* __restrict__ gamma,
                                            const float* __restrict__ beta,
                                            float* __restrict__ out) {
    __shared__ float ssc[OUTC], ssh[OUTC];
    int tid = threadIdx.x;
    if (tid < OUTC) {
        float mean = g_sum[tid] * (1.f / NN);
        float var  = g_sumsq[tid] * (1.f / NN) - mean * mean;
        float invs = rsqrtf(var + BN_EPS);
        float sc   = gamma[tid] * invs;
        ssc[tid] = sc;
        ssh[tid] = beta[tid] - mean * sc;
    }
    __syncthreads();

    int i4 = blockIdx.x * 256 + tid;
    if (i4 < NN * OUTC / 4) {
        int base = i4 * 4;
        int c = base & 63;
        float4 v = *(const float4*)&g_pre[base];
        v.x = fmaxf(fmaf(v.x, ssc[c],     ssh[c]),     0.f);
        v.y = fmaxf(fmaf(v.y, ssc[c + 1], ssh[c + 1]), 0.f);
        v.z = fmaxf(fmaf(v.z, ssc[c + 2], ssh[c + 2]), 0.f);
        v.w = fmaxf(fmaf(v.w, ssc[c + 3], ssh[c + 3]), 0.f);
        *(float4*)&out[base] = v;
    }
}

// ---------------- launch ----------------
extern "C" void kernel_launch(void* const* d_in, const int* in_sizes, int n_in,
                              void* d_out, int out_size) {
    const float* x    = (const float*)d_in[0];
    const float* emb  = (const float*)d_in[1];
    const void*  ei   = d_in[2];
    const float* linw = (const float*)d_in[3];
    const float* ai   = (const float*)d_in[4];
    const float* aj   = (const float*)d_in[5];
    const float* aei  = (const float*)d_in[6];
    const float* aej  = (const float*)d_in[7];
    const float* bias = (const float*)d_in[8];
    const float* gam  = (const float*)d_in[9];
    const float* bet  = (const float*)d_in[10];
    float* out = (float*)d_out;

    k_gemm<<<(NN + 127) / 128, 256>>>(x, linw, (const int*)ei);
    k_scal<<<(NN + 7) / 8, 256>>>(emb, ai, aj, aei, aej);
    k_agg<<<NN / 2, 64>>>(ei, bias);
    k_red<<<148, 1024>>>();
    k_bn<<<(NN * OUTC / 4 + 255) / 256, 256>>>(gam, bet, out);
}

// round 14
// speedup vs baseline: 1.5623x; 1.5623x over previous
#include <cuda_runtime.h>

#define NN   50000
#define TOPK 32
#define INC  128
#define OUTC 64
#define NEG_SLOPE 0.2f
#define BN_EPS 1e-5f

// ---------------- scratch (no allocations allowed) ----------------
__device__ float g_xlin[NN * OUTC];
__device__ float g_si[NN];
__device__ float g_sj[NN];
__device__ float g_pre[NN * OUTC];
__device__ float g_sum[OUTC];
__device__ float g_sumsq[OUTC];
__device__ int   g_is64;

// ---------------- f32x2 helpers (sm_100+ packed fp32) ----------------
__device__ __forceinline__ unsigned long long pack2(float a) {
    unsigned long long r;
    asm("mov.b64 %0, {%1, %1};" : "=l"(r) : "f"(a));
    return r;
}
__device__ __forceinline__ void ffma2(unsigned long long& c,
                                      unsigned long long a, unsigned long long b) {
    asm("fma.rn.f32x2 %0, %1, %2, %0;" : "+l"(c) : "l"(a), "l"(b));
}
__device__ __forceinline__ float2 u2f(unsigned long long v) {
    float2 f;
    asm("mov.b64 {%0, %1}, %2;" : "=f"(f.x), "=f"(f.y) : "l"(v));
    return f;
}

// ---------------- GEMM: x_lin = x @ W^T (R9-proven) ----------------
__global__ void __launch_bounds__(256) k_gemm(const float* __restrict__ x,
                                              const float* __restrict__ w,
                                              const int* __restrict__ ei32) {
    __shared__ float Ws[INC][68];
    __shared__ float xs[16][132];

    const int tid = threadIdx.x;
    const int m0  = blockIdx.x * 128;

    if (blockIdx.x == 0) {
        if (tid < OUTC) { g_sum[tid] = 0.f; g_sumsq[tid] = 0.f; }
        if (tid == 0) {
            int any = 0;
            #pragma unroll 1
            for (int i = 1; i < 128; i += 2) any |= ei32[i];
            g_is64 = (any == 0) ? 1 : 0;
        }
    }

    for (int idx = tid; idx < OUTC * INC; idx += 256) {
        int n = idx >> 7, k = idx & 127;
        Ws[k][n] = w[idx];
    }

    const int rg = tid & 31;
    const int cg = tid >> 5;

    unsigned long long acc[4][4];
    #pragma unroll
    for (int i = 0; i < 4; i++)
        #pragma unroll
        for (int j = 0; j < 4; j++) acc[i][j] = 0ull;

    for (int kc = 0; kc < INC; kc += 16) {
        __syncthreads();
        #pragma unroll
        for (int rr = 0; rr < 2; rr++) {
            int row = ((tid >> 2) & 63) + rr * 64;
            int k4  = (tid & 3) * 4;
            int gr  = m0 + row;
            float4 v = make_float4(0.f, 0.f, 0.f, 0.f);
            if (gr < NN) v = *(const float4*)&x[gr * INC + kc + k4];
            xs[k4 + 0][row] = v.x;
            xs[k4 + 1][row] = v.y;
            xs[k4 + 2][row] = v.z;
            xs[k4 + 3][row] = v.w;
        }
        __syncthreads();

        #pragma unroll
        for (int k = 0; k < 16; k++) {
            float4 a = *(const float4*)&xs[k][rg * 4];
            const ulonglong2* bp = (const ulonglong2*)&Ws[kc + k][cg * 8];
            ulonglong2 bA = bp[0];
            ulonglong2 bB = bp[1];
            unsigned long long bv[4] = {bA.x, bA.y, bB.x, bB.y};
            unsigned long long av[4] = {pack2(a.x), pack2(a.y), pack2(a.z), pack2(a.w)};
            #pragma unroll
            for (int i = 0; i < 4; i++)
                #pragma unroll
                for (int j = 0; j < 4; j++)
                    ffma2(acc[i][j], av[i], bv[j]);
        }
    }

    #pragma unroll
    for (int i = 0; i < 4; i++) {
        int m = m0 + rg * 4 + i;
        if (m < NN) {
            float2 p0 = u2f(acc[i][0]), p1 = u2f(acc[i][1]);
            float2 p2 = u2f(acc[i][2]), p3 = u2f(acc[i][3]);
            *(float4*)&g_xlin[m * OUTC + cg * 8]     = make_float4(p0.x, p0.y, p1.x, p1.y);
            *(float4*)&g_xlin[m * OUTC + cg * 8 + 4] = make_float4(p2.x, p2.y, p3.x, p3.y);
        }
    }
}

// ---------------- per-node attention scalars ----------------
__global__ void __launch_bounds__(256) k_scal(const float* __restrict__ emb,
                                              const float* __restrict__ ai,
                                              const float* __restrict__ aj,
                                              const float* __restrict__ aei,
                                              const float* __restrict__ aej) {
    int wrow = blockIdx.x * 8 + (threadIdx.x >> 5);
    int lane = threadIdx.x & 31;
    if (wrow >= NN) return;
    float x0 = g_xlin[wrow * OUTC + lane];
    float x1 = g_xlin[wrow * OUTC + 32 + lane];
    float e0 = emb[wrow * OUTC + lane];
    float e1 = emb[wrow * OUTC + 32 + lane];
    float si = x0 * ai[lane] + x1 * ai[lane + 32] + e0 * aei[lane] + e1 * aei[lane + 32];
    float sj = x0 * aj[lane] + x1 * aj[lane + 32] + e0 * aej[lane] + e1 * aej[lane + 32];
    #pragma unroll
    for (int o = 16; o; o >>= 1) {
        si += __shfl_xor_sync(0xffffffffu, si, o);
        sj += __shfl_xor_sync(0xffffffffu, sj, o);
    }
    if (lane == 0) { g_si[wrow] = si; g_sj[wrow] = sj; }
}

// ---------------- softmax + gather: one WARP per node, fp32 float2, MLP=8 ----
__global__ void __launch_bounds__(64) k_agg(const void* __restrict__ ei,
                                            const float* __restrict__ bias) {
    const int wid  = threadIdx.x >> 5;
    const int lane = threadIdx.x & 31;
    const int n    = blockIdx.x * 2 + wid;

    __shared__ float2 spack[2][34];

    int src;
    if (g_is64) src = (int)((const long long*)ei)[(long long)n * TOPK + lane];
    else        src = ((const int*)ei)[n * TOPK + lane];
    float si  = g_si[n];
    float sjn = g_sj[n];
    float a = si + g_sj[src];
    a = (a >= 0.f) ? a : NEG_SLOPE * a;
    float aself = si + sjn;
    aself = (aself >= 0.f) ? aself : NEG_SLOPE * aself;

    float m = fmaxf(a, aself);
    #pragma unroll
    for (int o = 16; o; o >>= 1) m = fmaxf(m, __shfl_xor_sync(0xffffffffu, m, o));
    float ex  = __expf(a - m);
    float exs = __expf(aself - m);
    float ssum = ex;
    #pragma unroll
    for (int o = 16; o; o >>= 1) ssum += __shfl_xor_sync(0xffffffffu, ssum, o);
    ssum += exs;
    float inv = 1.f / (ssum + 1e-16f);
    spack[wid][lane] = make_float2(ex * inv, __int_as_float(src));
    if (lane == 0) spack[wid][32] = make_float2(exs * inv, __int_as_float(n));
    __syncwarp();

    unsigned long long acc = 0ull;
    #pragma unroll
    for (int c0 = 0; c0 < TOPK; c0 += 8) {
        float2 p[8];
        #pragma unroll
        for (int c = 0; c < 8; c++) p[c] = spack[wid][c0 + c];
        unsigned long long v[8];
        #pragma unroll
        for (int c = 0; c < 8; c++) {
            int s = __float_as_int(p[c].y);
            v[c] = *(const unsigned long long*)&g_xlin[s * OUTC + lane * 2];
        }
        #pragma unroll
        for (int c = 0; c < 8; c++) ffma2(acc, pack2(p[c].x), v[c]);
    }
    {
        float2 p = spack[wid][32];
        int s = __float_as_int(p.y);
        unsigned long long v = *(const unsigned long long*)&g_xlin[s * OUTC + lane * 2];
        ffma2(acc, pack2(p.x), v);
    }
    float2 r  = u2f(acc);
    float2 b2 = *(const float2*)&bias[lane * 2];
    r.x += b2.x;
    r.y += b2.y;
    *(float2*)&g_pre[n * OUTC + lane * 2] = r;
}

// ---------------- BN reduction: ONE wave (148 blocks x 256) — R9-proven ----------------
__global__ void __launch_bounds__(256) k_red() {
    __shared__ float4 sa[256], sb[256];
    const int tid = threadIdx.x;
    const int total = gridDim.x * 256;            // 148*256 = 37888, mult of 16
    float4 s  = make_float4(0.f, 0.f, 0.f, 0.f);
    float4 s2 = make_float4(0.f, 0.f, 0.f, 0.f);
    for (int i4 = blockIdx.x * 256 + tid; i4 < NN * OUTC / 4; i4 += total) {
        float4 v = *(const float4*)&g_pre[i4 * 4];
        s.x += v.x; s.y += v.y; s.z += v.z; s.w += v.w;
        s2.x = fmaf(v.x, v.x, s2.x);
        s2.y = fmaf(v.y, v.y, s2.y);
        s2.z = fmaf(v.z, v.z, s2.z);
        s2.w = fmaf(v.w, v.w, s2.w);
    }
    sa[tid] = s; sb[tid] = s2;
    __syncthreads();
    #pragma unroll
    for (int off = 128; off >= 16; off >>= 1) {
        if (tid < off) {
            float4 qa = sa[tid + off], qb = sb[tid + off];
            float4 ra = sa[tid],       rb = sb[tid];
            ra.x += qa.x; ra.y += qa.y; ra.z += qa.z; ra.w += qa.w;
            rb.x += qb.x; rb.y += qb.y; rb.z += qb.z; rb.w += qb.w;
            sa[tid] = ra; sb[tid] = rb;
        }
        __syncthreads();
    }
    if (tid < 16) {
        float4 ra = sa[tid], rb = sb[tid];
        int c = tid * 4;
        atomicAdd(&g_sum[c],     ra.x);
        atomicAdd(&g_sum[c + 1], ra.y);
        atomicAdd(&g_sum[c + 2], ra.z);
        atomicAdd(&g_sum[c + 3], ra.w);
        atomicAdd(&g_sumsq[c],     rb.x);
        atomicAdd(&g_sumsq[c + 1], rb.y);
        atomicAdd(&g_sumsq[c + 2], rb.z);
        atomicAdd(&g_sumsq[c + 3], rb.w);
    }
}

// ---------------- BN stats (inline) + apply + ReLU ----------------
__global__ void __launch_bounds__(256) k_bn(const float* __restrict__ gamma,
                                            const float* __restrict__ beta,
                                            float* __restrict__ out) {
    __shared__ float ssc[OUTC], ssh[OUTC];
    int tid = threadIdx.x;
    if (tid < OUTC) {
        float mean = g_sum[tid] * (1.f / NN);
        float var  = g_sumsq[tid] * (1.f / NN) - mean * mean;
        float invs = rsqrtf(var + BN_EPS);
        float sc   = gamma[tid] * invs;
        ssc[tid] = sc;
        ssh[tid] = beta[tid] - mean * sc;
    }
    __syncthreads();

    int i4 = blockIdx.x * 256 + tid;
    if (i4 < NN * OUTC / 4) {
        int base = i4 * 4;
        int c = base & 63;
        float4 v = *(const float4*)&g_pre[base];
        v.x = fmaxf(fmaf(v.x, ssc[c],     ssh[c]),     0.f);
        v.y = fmaxf(fmaf(v.y, ssc[c + 1], ssh[c + 1]), 0.f);
        v.z = fmaxf(fmaf(v.z, ssc[c + 2], ssh[c + 2]), 0.f);
        v.w = fmaxf(fmaf(v.w, ssc[c + 3], ssh[c + 3]), 0.f);
        *(float4*)&out[base] = v;
    }
}

// ---------------- launch ----------------
extern "C" void kernel_launch(void* const* d_in, const int* in_sizes, int n_in,
                              void* d_out, int out_size) {
    const float* x    = (const float*)d_in[0];
    const float* emb  = (const float*)d_in[1];
    const void*  ei   = d_in[2];
    const float* linw = (const float*)d_in[3];
    const float* ai   = (const float*)d_in[4];
    const float* aj   = (const float*)d_in[5];
    const float* aei  = (const float*)d_in[6];
    const float* aej  = (const float*)d_in[7];
    const float* bias = (const float*)d_in[8];
    const float* gam  = (const float*)d_in[9];
    const float* bet  = (const float*)d_in[10];
    float* out = (float*)d_out;

    k_gemm<<<(NN + 127) / 128, 256>>>(x, linw, (const int*)ei);
    k_scal<<<(NN + 7) / 8, 256>>>(emb, ai, aj, aei, aej);
    k_agg<<<NN / 2, 64>>>(ei, bias);
    k_red<<<148, 256>>>();
    k_bn<<<(NN * OUTC / 4 + 255) / 256, 256>>>(gam, bet, out);
}